// round 1
// baseline (speedup 1.0000x reference)
#include <cuda_runtime.h>
#include <math.h>

#define THREADS 128
#define TILES   4

typedef unsigned long long u64;

__device__ __forceinline__ u64 ffma2(u64 a, u64 b, u64 c) {
    u64 d;
    asm("fma.rn.f32x2 %0, %1, %2, %3;" : "=l"(d) : "l"(a), "l"(b), "l"(c));
    return d;
}
__device__ __forceinline__ u64 dup2(float x) {
    u64 d; unsigned u = __float_as_uint(x);
    asm("mov.b64 %0, {%1, %2};" : "=l"(d) : "r"(u), "r"(u));
    return d;
}
__device__ __forceinline__ void unpack2(u64 v, float &lo, float &hi) {
    unsigned a, b;
    asm("mov.b64 {%0, %1}, %2;" : "=r"(a), "=r"(b) : "l"(v));
    lo = __uint_as_float(a); hi = __uint_as_float(b);
}
__device__ __forceinline__ u64 pack2(float a, float b) {
    u64 d;
    asm("mov.b64 %0, {%1, %2};" : "=l"(d) : "r"(__float_as_uint(a)), "r"(__float_as_uint(b)));
    return d;
}

// ---- shared memory layout (float offsets) ----
#define C_TILE_SZ  (128 * 65)            /* padded c tile: 128 rows x 64, stride 65 */
#define STAGE_SZ   9220
#define W1_OFF     0                     /* [68][64] float2: (W[2p][k],W[2p+1][k])*s1  -> 8704 floats */
#define B1_OFF     8704                  /* 128 floats (pairs read as float2)          */
#define W2H_OFF    8832                  /* [128] float2: (W2[0][j],W2[1][j])*s2       -> 256 floats */
#define W2C_OFF    9088                  /* [64]  float2: (W2[0][128+k],W2[1][128+k])*s2 -> 128 floats */
#define B2_OFF     9216                  /* 2 floats + pad */
#define SMEM_FLOATS (C_TILE_SZ + 2 * STAGE_SZ)

__global__ __launch_bounds__(THREADS, 2)
void coupling_kernel(const float* __restrict__ coords,
                     const float* __restrict__ c,
                     const float* __restrict__ Wx1, const float* __restrict__ bx1,
                     const float* __restrict__ Wx2, const float* __restrict__ bx2,
                     const float* __restrict__ Wy1, const float* __restrict__ by1,
                     const float* __restrict__ Wy2, const float* __restrict__ by2,
                     float* __restrict__ out, long M)
{
    extern __shared__ float sm[];
    const int tid = threadIdx.x;
    const float s1 = 1.0f / sqrtf(68.0f);
    const float s2 = 1.0f / sqrtf(192.0f);

    // ---- pack + pre-scale weights into SMEM (once per block) ----
    #pragma unroll
    for (int s = 0; s < 2; s++) {
        const float* W1g = s ? Wy1 : Wx1;
        const float* b1g = s ? by1 : bx1;
        const float* W2g = s ? Wy2 : Wx2;
        const float* b2g = s ? by2 : bx2;
        float* sb = sm + C_TILE_SZ + s * STAGE_SZ;
        for (int idx = tid; idx < 68 * 64; idx += THREADS) {
            int k = idx >> 6, p = idx & 63;
            sb[W1_OFF + 2 * idx + 0] = W1g[(2 * p)     * 68 + k] * s1;
            sb[W1_OFF + 2 * idx + 1] = W1g[(2 * p + 1) * 68 + k] * s1;
        }
        for (int j = tid; j < 128; j += THREADS) {
            sb[B1_OFF + j] = b1g[j];
            sb[W2H_OFF + 2 * j + 0] = W2g[j]       * s2;
            sb[W2H_OFF + 2 * j + 1] = W2g[192 + j] * s2;
        }
        for (int k = tid; k < 64; k += THREADS) {
            sb[W2C_OFF + 2 * k + 0] = W2g[128 + k]       * s2;
            sb[W2C_OFF + 2 * k + 1] = W2g[192 + 128 + k] * s2;
        }
        if (tid == 0) { sb[B2_OFF] = b2g[0]; sb[B2_OFF + 1] = b2g[1]; }
    }

    const long tile0 = (long)blockIdx.x * TILES;
    for (int t = 0; t < TILES; t++) {
        long base = (tile0 + t) * 128;
        if (base >= M) break;                 // uniform across block
        __syncthreads();                      // protect previous tile reads + weight init
        // ---- stage c tile through SMEM (coalesced gmem, pad-65 smem) ----
        for (int idx = tid; idx < 128 * 64; idx += THREADS) {
            int rr = idx >> 6, kk = idx & 63;
            long r = base + rr;
            sm[rr * 65 + kk] = (r < M) ? c[r * 64 + kk] : 0.0f;
        }
        __syncthreads();

        long r = base + tid;
        if (r < M) {
            float cx[64];
            #pragma unroll
            for (int k = 0; k < 64; k++) cx[k] = sm[tid * 65 + k];

            float2 xy = *((const float2*)coords + r);
            float cur_in = xy.x;   // stage 0 reads x, updates y
            float cur_up = xy.y;
            float lsum = 0.0f;

            #pragma unroll
            for (int s = 0; s < 2; s++) {
                const float* sb = sm + C_TILE_SZ + s * STAGE_SZ;
                // sinusoidals of cur_in/10 : [sin a, sin 2a, cos a, cos 2a]
                float a = cur_in * 0.1f;
                float sa, ca;
                sincosf(a, &sa, &ca);
                float s2a = 2.0f * sa * ca;
                float c2a = 1.0f - 2.0f * sa * sa;
                u64 hs[4] = { dup2(sa), dup2(s2a), dup2(ca), dup2(c2a) };

                const u64* W1  = (const u64*)(sb + W1_OFF);
                const u64* B1  = (const u64*)(sb + B1_OFF);
                const u64* W2H = (const u64*)(sb + W2H_OFF);
                const u64* W2C = (const u64*)(sb + W2C_OFF);
                u64 oacc = *(const u64*)(sb + B2_OFF);     // (o0, o1)

                #pragma unroll
                for (int pb = 0; pb < 8; pb++) {
                    u64 acc[8];
                    #pragma unroll
                    for (int q = 0; q < 8; q++) acc[q] = B1[pb * 8 + q];

                    // sinusoidal columns (k = 0..3)
                    #pragma unroll
                    for (int k = 0; k < 4; k++) {
                        const ulonglong2* wrow =
                            (const ulonglong2*)(W1 + k * 64) + pb * 4;
                        #pragma unroll
                        for (int q2 = 0; q2 < 4; q2++) {
                            ulonglong2 w = wrow[q2];
                            acc[2 * q2 + 0] = ffma2(hs[k], w.x, acc[2 * q2 + 0]);
                            acc[2 * q2 + 1] = ffma2(hs[k], w.y, acc[2 * q2 + 1]);
                        }
                    }
                    // conditioning columns (k = 4..67)
                    #pragma unroll
                    for (int k = 0; k < 64; k++) {
                        u64 cd = dup2(cx[k]);
                        const ulonglong2* wrow =
                            (const ulonglong2*)(W1 + (4 + k) * 64) + pb * 4;
                        #pragma unroll
                        for (int q2 = 0; q2 < 4; q2++) {
                            ulonglong2 w = wrow[q2];
                            acc[2 * q2 + 0] = ffma2(cd, w.x, acc[2 * q2 + 0]);
                            acc[2 * q2 + 1] = ffma2(cd, w.y, acc[2 * q2 + 1]);
                        }
                    }
                    // activation + fused layer-2 h-part (h never stored)
                    #pragma unroll
                    for (int q = 0; q < 8; q++) {
                        float v0, v1; unpack2(acc[q], v0, v1);
                        float h0 = fmaxf(v0, 0.0f) * 1.41421356f + fminf(v0, 0.0f) * 0.28284271f;
                        float h1 = fmaxf(v1, 0.0f) * 1.41421356f + fminf(v1, 0.0f) * 0.28284271f;
                        int j = (pb * 8 + q) * 2;
                        oacc = ffma2(dup2(h0), W2H[j],     oacc);
                        oacc = ffma2(dup2(h1), W2H[j + 1], oacc);
                    }
                }
                // layer-2 c-part
                #pragma unroll
                for (int k = 0; k < 64; k++)
                    oacc = ffma2(dup2(cx[k]), W2C[k], oacc);

                float o0, o1; unpack2(oacc, o0, o1);
                float ls = fminf(fmaxf(o0, -5.0f), 5.0f);
                cur_up = cur_up * __expf(ls) + o1;
                lsum += ls;
                // swap roles for next stage
                float tmp = cur_in; cur_in = cur_up; cur_up = tmp;
            }
            // after stage1 swap: cur_in = x_final, cur_up = y_final
            out[2 * r]     = cur_in;
            out[2 * r + 1] = cur_up;
            out[2 * M + r] = lsum;
        }
    }
}

extern "C" void kernel_launch(void* const* d_in, const int* in_sizes, int n_in,
                              void* d_out, int out_size) {
    const float* coords = (const float*)d_in[0];
    const float* c      = (const float*)d_in[1];
    const float* Wx1    = (const float*)d_in[2];
    const float* bx1    = (const float*)d_in[3];
    const float* Wx2    = (const float*)d_in[4];
    const float* bx2    = (const float*)d_in[5];
    const float* Wy1    = (const float*)d_in[6];
    const float* by1    = (const float*)d_in[7];
    const float* Wy2    = (const float*)d_in[8];
    const float* by2    = (const float*)d_in[9];
    float* out = (float*)d_out;

    long M = (long)in_sizes[1] / 64;
    long rowsPerBlock = (long)THREADS * TILES;
    int grid = (int)((M + rowsPerBlock - 1) / rowsPerBlock);
    size_t smem = (size_t)SMEM_FLOATS * sizeof(float);

    cudaFuncSetAttribute(coupling_kernel,
                         cudaFuncAttributeMaxDynamicSharedMemorySize, (int)smem);
    coupling_kernel<<<grid, THREADS, smem>>>(coords, c,
                                             Wx1, bx1, Wx2, bx2,
                                             Wy1, by1, Wy2, by2,
                                             out, M);
}

// round 4
// speedup vs baseline: 4.9559x; 4.9559x over previous
#include <cuda_runtime.h>
#include <math.h>
#include <cstdint>

#define THREADS 128

typedef unsigned long long u64;
typedef unsigned int u32;

// ---------------- f32x2 helpers ----------------
__device__ __forceinline__ u64 ffma2(u64 a, u64 b, u64 c) {
    u64 d; asm("fma.rn.f32x2 %0, %1, %2, %3;" : "=l"(d) : "l"(a), "l"(b), "l"(c)); return d;
}
__device__ __forceinline__ u64 mul2(u64 a, u64 b) {
    u64 d; asm("mul.rn.f32x2 %0, %1, %2;" : "=l"(d) : "l"(a), "l"(b)); return d;
}
__device__ __forceinline__ u64 add2(u64 a, u64 b) {
    u64 d; asm("add.rn.f32x2 %0, %1, %2;" : "=l"(d) : "l"(a), "l"(b)); return d;
}
__device__ __forceinline__ u64 dup2(float x) {
    u64 d; unsigned u = __float_as_uint(x);
    asm("mov.b64 %0, {%1, %2};" : "=l"(d) : "r"(u), "r"(u)); return d;
}
__device__ __forceinline__ u64 pack2(float a, float b) {
    u64 d; asm("mov.b64 %0, {%1, %2};" : "=l"(d) : "r"(__float_as_uint(a)), "r"(__float_as_uint(b))); return d;
}
__device__ __forceinline__ void unpack2(u64 v, float &lo, float &hi) {
    unsigned a, b; asm("mov.b64 {%0, %1}, %2;" : "=r"(a), "=r"(b) : "l"(v));
    lo = __uint_as_float(a); hi = __uint_as_float(b);
}
__device__ __forceinline__ u32 f2tf32(float f) {
    u32 r; asm("cvt.rna.tf32.f32 %0, %1;" : "=r"(r) : "f"(f)); return r;
}

// mma.sync m16n8k8 tf32 (portable sm_80+ path; runs on tensor pipe)
__device__ __forceinline__ void mma8(float* acc, const u32* a, u64 b) {
    u32 b0 = (u32)b, b1 = (u32)(b >> 32);
    asm volatile("mma.sync.aligned.m16n8k8.row.col.f32.tf32.tf32.f32 "
                 "{%0,%1,%2,%3}, {%4,%5,%6,%7}, {%8,%9}, {%0,%1,%2,%3};"
                 : "+f"(acc[0]), "+f"(acc[1]), "+f"(acc[2]), "+f"(acc[3])
                 : "r"(a[0]), "r"(a[1]), "r"(a[2]), "r"(a[3]), "r"(b0), "r"(b1));
}

__device__ __forceinline__ float qredf(float v) {
    v += __shfl_xor_sync(0xffffffffu, v, 1);
    v += __shfl_xor_sync(0xffffffffu, v, 2);
    return v;
}

// ---------------- smem layout (bytes) ----------------
#define SM_XY    0        /* float2[128]           1024  */
#define SM_SF    1024     /* float4[128]           2048  */
#define SM_Q     3072     /* float4[128]           2048  */
#define SM_RES   5120     /* float4[128]           2048  */
#define SM_META  7168     /* u64[128][8] swizzled  8192  */
#define SM_W2C   15360    /* ulonglong2[64]        1024  */
#define SM_A     16384    /* u32 tf32 [128][64] xor-swz  32768 */
#define SM_BP    49152    /* u64 [256][32] xor-swz 65536 */
#define SMEM_BYTES 114688

#define LK_A 0.84852813742385703f  /* 0.6*sqrt(2) */
#define LK_B 0.56568542494923801f  /* 0.4*sqrt(2) */

__global__ __launch_bounds__(THREADS, 2)
void coupling_mma_kernel(const float* __restrict__ coords,
                         const float* __restrict__ c,
                         const float* __restrict__ Wx1, const float* __restrict__ bx1,
                         const float* __restrict__ Wx2, const float* __restrict__ bx2,
                         const float* __restrict__ Wy1, const float* __restrict__ by1,
                         const float* __restrict__ Wy2, const float* __restrict__ by2,
                         float* __restrict__ out, long M)
{
    extern __shared__ char smem[];
    const int tid  = threadIdx.x;
    const int lane = tid & 31;
    const int warp = tid >> 5;
    const int g    = lane >> 2;     // 0..7
    const int tq   = lane & 3;      // 0..3
    const long base = (long)blockIdx.x * 128;

    const float s1 = 1.0f / sqrtf(68.0f);
    const float s2 = 1.0f / sqrtf(192.0f);

    float2* XY = (float2*)(smem + SM_XY);
    float4* SF = (float4*)(smem + SM_SF);
    float4* QS = (float4*)(smem + SM_Q);
    float4* RES = (float4*)(smem + SM_RES);
    u64*    MP = (u64*)(smem + SM_META);
    ulonglong2* W2C = (ulonglong2*)(smem + SM_W2C);
    u32*    AS = (u32*)(smem + SM_A);
    u64*    BP = (u64*)(smem + SM_BP);

    // ---------- staging ----------
    // A: c[128 x 64] -> tf32 bits, layout row*64 + (k ^ ((row&7)<<2))
    #pragma unroll
    for (int i = 0; i < 16; i++) {
        int idx = tid + i * THREADS;          // float4 index
        int row = idx >> 4;
        int k4  = (idx & 15) << 2;
        long gr = base + row;
        float4 v = make_float4(0.f, 0.f, 0.f, 0.f);
        if (gr < M) v = *(const float4*)(c + gr * 64 + k4);
        uint4 tv = { f2tf32(v.x), f2tf32(v.y), f2tf32(v.z), f2tf32(v.w) };
        *(uint4*)(AS + row * 64 + (k4 ^ ((row & 7) << 2))) = tv;
    }
    // Bpack: n = output j (0..255), pair index j8 = kk*4+t -> (W[n][k0], W[n][k0+4])
    // FULL coverage: 8192 u64 elements = 64 iterations of 128 threads.
    #pragma unroll
    for (int i = 0; i < 64; i++) {
        int idx = tid + i * THREADS;          // u64 element index 0..8191
        int n  = idx >> 5;
        int j8 = idx & 31;
        int kk = j8 >> 2, t = j8 & 3;
        int k0 = kk * 8 + t;
        const float* Wg = (n < 128) ? Wx1 : Wy1;
        int row = n & 127;
        u32 lo = f2tf32(Wg[row * 68 + 4 + k0] * s1);
        u32 hi = f2tf32(Wg[row * 68 + 4 + k0 + 4] * s1);
        BP[n * 32 + (j8 ^ ((n & 3) << 2))] = ((u64)hi << 32) | lo;
    }
    // meta pairs: jp = j>>1, slots {A0..A3 (w1s pairs), H0, H1, BB}, slot stored at s^(jp&3)
    {
        int jp = tid;                          // 0..127
        int j0 = 2 * jp;
        int st = j0 >> 7;
        int jj0 = j0 & 127, jj1 = jj0 + 1;
        const float* W1g = st ? Wy1 : Wx1;
        const float* W2g = st ? Wy2 : Wx2;
        const float* b1g = st ? by1 : bx1;
        int sw = jp & 3;
        u64* mp = MP + jp * 8;
        #pragma unroll
        for (int s = 0; s < 4; s++)
            mp[s ^ sw] = pack2(W1g[jj0 * 68 + s] * s1, W1g[jj1 * 68 + s] * s1);
        mp[4 ^ sw] = pack2(W2g[jj0] * s2, W2g[jj1] * s2);
        mp[5 ^ sw] = pack2(W2g[192 + jj0] * s2, W2g[192 + jj1] * s2);
        mp[6 ^ sw] = pack2(b1g[jj0], b1g[jj1]);
    }
    if (tid < 64) {
        int k = tid;
        ulonglong2 w;
        w.x = pack2(Wx2[128 + k] * s2, Wx2[192 + 128 + k] * s2);
        w.y = pack2(Wy2[128 + k] * s2, Wy2[192 + 128 + k] * s2);
        W2C[k] = w;
    }
    // coords + stage-0 sin features (row = tid)
    {
        long rr = base + tid;
        float2 xy = make_float2(0.f, 0.f);
        if (rr < M) xy = ((const float2*)coords)[rr];
        XY[tid] = xy;
        float a = xy.x * 0.1f, sa, ca;
        sincosf(a, &sa, &ca);
        SF[tid] = make_float4(sa, 2.0f * sa * ca, ca, 1.0f - 2.0f * sa * sa);
    }
    __syncthreads();

    // ---------- per-row q = c @ W2c (+ b2), row = tid ----------
    {
        int row = tid;
        int swz = (row & 7) << 2;
        u64 qx = pack2(0.f, 0.f), qy = qx;
        #pragma unroll
        for (int k4 = 0; k4 < 64; k4 += 4) {
            uint4 cv = *(uint4*)(AS + row * 64 + (k4 ^ swz));
            float cf[4] = { __uint_as_float(cv.x), __uint_as_float(cv.y),
                            __uint_as_float(cv.z), __uint_as_float(cv.w) };
            #pragma unroll
            for (int q = 0; q < 4; q++) {
                ulonglong2 w = W2C[k4 + q];
                u64 cd = dup2(cf[q]);
                qx = ffma2(cd, w.x, qx);
                qy = ffma2(cd, w.y, qy);
            }
        }
        float qx0, qx1, qy0, qy1;
        unpack2(qx, qx0, qx1); unpack2(qy, qy0, qy1);
        QS[tid] = make_float4(qx0 + bx2[0], qx1 + bx2[1], qy0 + by2[0], qy1 + by2[1]);
    }
    __syncwarp();

    // ---------- A fragments (cached, reused both stages) ----------
    u32 afr[2][8][4];
    {
        const int swz = g << 2;   // rows used always have row&7 == g
        #pragma unroll
        for (int mt = 0; mt < 2; mt++) {
            int r0 = warp * 32 + mt * 16 + g;
            #pragma unroll
            for (int kk = 0; kk < 8; kk++) {
                int k0 = kk * 8 + tq;
                afr[mt][kk][0] = AS[r0 * 64 + (k0 ^ swz)];
                afr[mt][kk][1] = AS[(r0 + 8) * 64 + (k0 ^ swz)];
                afr[mt][kk][2] = AS[r0 * 64 + ((k0 + 4) ^ swz)];
                afr[mt][kk][3] = AS[(r0 + 8) * 64 + ((k0 + 4) ^ swz)];
            }
        }
    }

    // rows owned by this thread (quad-redundant)
    int R[4];
    #pragma unroll
    for (int ri = 0; ri < 4; ri++) R[ri] = warp * 32 + ri * 8 + g;

    float cin[4], cup[4], lsum[4];
    #pragma unroll
    for (int ri = 0; ri < 4; ri++) {
        float2 xy = XY[R[ri]];
        cin[ri] = xy.x; cup[ri] = xy.y; lsum[ri] = 0.0f;
    }

    const u64 lkA = dup2(LK_A), lkB = dup2(LK_B);
    const u64 ABSM = 0x7FFFFFFF7FFFFFFFull;

    for (int st = 0; st < 2; st++) {
        // per-row sin features
        float4 sfr[4];
        #pragma unroll
        for (int ri = 0; ri < 4; ri++) sfr[ri] = SF[R[ri]];

        u64 po0[4], po1[4];
        #pragma unroll
        for (int ri = 0; ri < 4; ri++) { po0[ri] = pack2(0.f, 0.f); po1[ri] = po0[ri]; }

        for (int chunk = 0; chunk < 4; chunk++) {
            int nbase = st * 16 + chunk * 4;
            float acc[2][4][4];
            #pragma unroll
            for (int mt = 0; mt < 2; mt++)
                #pragma unroll
                for (int nt = 0; nt < 4; nt++)
                    #pragma unroll
                    for (int q = 0; q < 4; q++) acc[mt][nt][q] = 0.0f;

            #pragma unroll
            for (int kk = 0; kk < 8; kk++) {
                u64 bfr[4];
                #pragma unroll
                for (int nt = 0; nt < 4; nt++) {
                    int n = (nbase + nt) * 8 + g;
                    int j8 = (kk * 4 + tq) ^ ((n & 3) << 2);
                    bfr[nt] = BP[n * 32 + j8];
                }
                #pragma unroll
                for (int nt = 0; nt < 4; nt++) {
                    mma8(acc[0][nt], afr[0][kk], bfr[nt]);
                    mma8(acc[1][nt], afr[1][kk], bfr[nt]);
                }
            }

            // fragment epilogue: bias + sin features, leaky, dot into o partials
            #pragma unroll
            for (int nt = 0; nt < 4; nt++) {
                int jp = st * 64 + chunk * 16 + nt * 4 + tq;
                const u64* mp = MP + jp * 8;
                u64 A0 = mp[0 ^ tq], A1 = mp[1 ^ tq], A2 = mp[2 ^ tq], A3 = mp[3 ^ tq];
                u64 H0 = mp[4 ^ tq], H1 = mp[5 ^ tq], BB = mp[6 ^ tq];
                #pragma unroll
                for (int mt = 0; mt < 2; mt++) {
                    #pragma unroll
                    for (int h = 0; h < 2; h++) {
                        int ri = mt * 2 + h;
                        float4 sf = sfr[ri];
                        u64 v = pack2(acc[mt][nt][2 * h + 0], acc[mt][nt][2 * h + 1]);
                        v = add2(v, BB);
                        v = ffma2(dup2(sf.x), A0, v);
                        v = ffma2(dup2(sf.y), A1, v);
                        v = ffma2(dup2(sf.z), A2, v);
                        v = ffma2(dup2(sf.w), A3, v);
                        u64 av = v & ABSM;
                        u64 hh = ffma2(lkA, v, mul2(lkB, av));
                        po0[ri] = ffma2(hh, H0, po0[ri]);
                        po1[ri] = ffma2(hh, H1, po1[ri]);
                    }
                }
            }
        }

        // reduce + coordinate update
        #pragma unroll
        for (int ri = 0; ri < 4; ri++) {
            float a0, a1, b0, b1;
            unpack2(po0[ri], a0, a1);
            unpack2(po1[ri], b0, b1);
            float o0 = qredf(a0 + a1);
            float o1 = qredf(b0 + b1);
            float4 qv = QS[R[ri]];
            o0 += st ? qv.z : qv.x;
            o1 += st ? qv.w : qv.y;
            float ls = fminf(fmaxf(o0, -5.0f), 5.0f);
            float up_new = cup[ri] * __expf(ls) + o1;
            lsum[ri] += ls;
            cup[ri] = cin[ri];
            cin[ri] = up_new;     // swap: new value becomes next stage input
        }

        if (st == 0) {
            #pragma unroll
            for (int ri = 0; ri < 4; ri++) {
                float a = cin[ri] * 0.1f, sa, ca;
                sincosf(a, &sa, &ca);
                if (tq == 0)
                    SF[R[ri]] = make_float4(sa, 2.0f * sa * ca, ca, 1.0f - 2.0f * sa * sa);
            }
            __syncwarp();
        }
    }

    // after stage 1: cin = x_final, cup = y_final
    if (tq == 0) {
        #pragma unroll
        for (int ri = 0; ri < 4; ri++)
            RES[R[ri]] = make_float4(cin[ri], cup[ri], lsum[ri], 0.0f);
    }
    __syncthreads();

    long rr = base + tid;
    if (rr < M) {
        float4 rv = RES[tid];
        ((float2*)out)[rr] = make_float2(rv.x, rv.y);
        out[2 * M + rr] = rv.z;
    }
}

extern "C" void kernel_launch(void* const* d_in, const int* in_sizes, int n_in,
                              void* d_out, int out_size) {
    const float* coords = (const float*)d_in[0];
    const float* c      = (const float*)d_in[1];
    const float* Wx1    = (const float*)d_in[2];
    const float* bx1    = (const float*)d_in[3];
    const float* Wx2    = (const float*)d_in[4];
    const float* bx2    = (const float*)d_in[5];
    const float* Wy1    = (const float*)d_in[6];
    const float* by1    = (const float*)d_in[7];
    const float* Wy2    = (const float*)d_in[8];
    const float* by2    = (const float*)d_in[9];
    float* out = (float*)d_out;

    long M = (long)in_sizes[1] / 64;
    int grid = (int)((M + 127) / 128);

    cudaFuncSetAttribute(coupling_mma_kernel,
                         cudaFuncAttributeMaxDynamicSharedMemorySize, SMEM_BYTES);
    coupling_mma_kernel<<<grid, THREADS, SMEM_BYTES>>>(coords, c,
                                                       Wx1, bx1, Wx2, bx2,
                                                       Wy1, by1, Wy2, by2,
                                                       out, M);
}